// round 15
// baseline (speedup 1.0000x reference)
#include <cuda_runtime.h>
#include <math.h>

#define M_ROWS  131072
#define N_CODES 2048
#define K_DIM   256
#define KW      64            // int words per row (4 int8 per word)
#define BM 64
#define BN 64
#define TM 4
#define TN 2
#define PITCH 68              // ints per k-word row in smem (mult of 4)
#define MW    64              // mask words per row (2048 bits)

#define OFF_Q    1
#define OFF_PERP 33554433
#define OFF_ENC  33554434

#define EPI_BLOCKS (M_ROWS / 8)

#define MARGIN  2e-3f
#define S_E     260096.0f     // 127 * 2048 (exact in fp32)

// ---- phase1 dynamic smem (ints): A | B0 | B1, each 64*PITCH ----
#define TILE_INTS (KW * PITCH)
#define SM_TOTAL  (3 * TILE_INTS * 4)

// -------- device scratch (no allocations allowed) --------
__device__ int      g_indices[M_ROWS];
__device__ int      g_hist[N_CODES];
__device__ float    g_cbnorm[N_CODES];
__device__ float    g_cbn4[N_CODES];   // cbnorm + 4 (phase1 fast path)
__device__ float    g_xnorm[M_ROWS];
__device__ float    g_xsx[M_ROWS];     // 127/max|x| pack scale
__device__ float    g_xdq[M_ROWS];     // max|x|/(127*S_E) dequant factor
__device__ double   g_part[EPI_BLOCKS];
__device__ int      g_cbi[N_CODES * KW];    // int8-packed codebook (512 KB)
__device__ int      g_xi8[M_ROWS * KW];     // int8-packed inputs  (32 MB)
__device__ unsigned g_mask[M_ROWS * MW];    // candidate bitmask    (32 MB)

// ============================================================
// Kernel 1: exact codebook norms (reference fp32 rounding emulation)
// + int8 codebook pack + zero histogram. One thread per code.
// ============================================================
__global__ void vq_init(const float* __restrict__ CB) {
    int gid = blockIdx.x * blockDim.x + threadIdx.x;
    if (gid >= N_CODES) return;
    const float* row = CB + (long)gid * K_DIM;
    float s = 0.f;
    for (int w = 0; w < KW; w++) {
        int pack = 0;
#pragma unroll
        for (int b = 0; b < 4; b++) {
            float v = row[w * 4 + b];
            s = __fadd_rn(s, __fmul_rn(v, v));   // no FMA contraction
            int q = __float2int_rn(v * S_E);     // |e|<=1/2048 -> |q|<=127
            pack |= (q & 0xFF) << (b * 8);
        }
        g_cbi[gid * KW + w] = pack;
    }
    g_cbnorm[gid] = s;
    g_cbn4[gid]   = s + 4.0f;
    g_hist[gid] = 0;
}

// ============================================================
// Kernel 1b: per-row ||x||^2 exact scalar-sequential emulation
// + per-row max|x| -> pack/dequant scales.
// ============================================================
__global__ void vq_xnorm(const float* __restrict__ X) {
    __shared__ float sh[256][33];
    const int tid = threadIdx.x;
    const long r0 = (long)blockIdx.x * 256;
    float acc = 0.f;
    float mx = 1e-20f;
    for (int c0 = 0; c0 < K_DIM; c0 += 32) {
        for (int idx = tid; idx < 256 * 32; idx += 256) {
            int row = idx >> 5, col = idx & 31;
            sh[row][col] = X[(r0 + row) * K_DIM + c0 + col];
        }
        __syncthreads();
#pragma unroll
        for (int c = 0; c < 32; c++) {
            float v = sh[tid][c];
            acc = __fadd_rn(acc, __fmul_rn(v, v));
            mx = fmaxf(mx, fabsf(v));
        }
        __syncthreads();
    }
    g_xnorm[r0 + tid] = acc;
    g_xsx[r0 + tid] = 127.0f / mx;
    g_xdq[r0 + tid] = mx * (1.0f / S_E / 127.0f);
}

// ============================================================
// Kernel 1c: pack X to int8 (one int word per thread) + zero the
// candidate mask (same index space: MW == KW words per row).
// ============================================================
__global__ void vq_xpack(const float* __restrict__ X) {
    const int gid = blockIdx.x * blockDim.x + threadIdx.x;   // word index
    const int row = gid >> 6;
    const float sx = g_xsx[row];
    float4 v = *(const float4*)(X + (long)gid * 4);
    int q0 = __float2int_rn(v.x * sx);
    int q1 = __float2int_rn(v.y * sx);
    int q2 = __float2int_rn(v.z * sx);
    int q3 = __float2int_rn(v.w * sx);
    g_xi8[gid] = (q0 & 0xFF) | ((q1 & 0xFF) << 8) | ((q2 & 0xFF) << 16)
               | (q3 << 24);
    g_mask[gid] = 0u;
}

// ============================================================
// 64-row x 64-word tile loader, conflict-free stores.
// Thread: row = tid>>3 (0..63), wslot = tid&7; words w = wslot + 8q.
// LDG: 32 lanes/q span 4 rows x 32B = coalesced 128B.
// STS bank = (4*(w mod 8) + row) mod 32 -> 32 distinct banks/warp.
// ============================================================
__device__ __forceinline__ void load_tile64(const int* __restrict__ gsrc,
                                            int* __restrict__ dst, int tid) {
    const int row = tid >> 3, ws = tid & 7;
    const int* src = gsrc + row * KW + ws;
#pragma unroll
    for (int q = 0; q < 8; q++)
        dst[(ws + 8 * q) * PITCH + row] = src[8 * q];
}

// ============================================================
// Kernel 2 (phase 1): int8 DP4A GEMM + candidate filter.
// 512 thr, 3 CTAs/SM (12 warps/SMSP): warp ty owns rows ty*4..+3,
// lane tx owns codes tx*2..+1 of a 64-code tile. 8 acc regs ->
// ~34 regs/thread -> RF allows 48 warps/SM (75% occ). Per w-iter:
// 1 LDS.128(A bcast) + 1 LDS.64(B) + 8 DP4A -> DP4A-pipe-bound.
// Double-buffered B, running row-min via REDUX, RED.OR bitmask.
// ============================================================
__global__ void __launch_bounds__(512, 3)
vq_phase1() {
    extern __shared__ int sm[];
    int* As  = sm;
    int* Bs0 = sm + TILE_INTS;
    int* Bs1 = sm + 2 * TILE_INTS;

    const int tid = threadIdx.x;
    const int tx = tid & 31;            // lane: 2 codes
    const int ty = tid >> 5;            // warp: 4 rows (0..15)
    const long row0 = (long)blockIdx.x * BM;
    const int ty4 = ty * 4, tx2 = tx * 2;

    float m2r[TM], rowmin[TM];
#pragma unroll
    for (int i = 0; i < TM; i++) {
        m2r[i] = -2.0f * g_xdq[row0 + ty4 + i];
        rowmin[i] = INFINITY;
    }

    load_tile64(g_xi8 + row0 * KW, As, tid);
    load_tile64(g_cbi, Bs0, tid);
    __syncthreads();

    for (int nt = 0; nt < N_CODES / BN; ++nt) {
        int* cur = (nt & 1) ? Bs1 : Bs0;
        int* nxt = (nt & 1) ? Bs0 : Bs1;
        if (nt + 1 < N_CODES / BN)
            load_tile64(g_cbi + (nt + 1) * BN * KW, nxt, tid);

        int acc[TM][TN];
#pragma unroll
        for (int i = 0; i < TM; i++)
#pragma unroll
            for (int j = 0; j < TN; j++) acc[i][j] = 0;

#pragma unroll 8
        for (int w = 0; w < KW; w++) {
            int4 a = *(const int4*)(As + w * PITCH + ty4);   // broadcast
            int2 b = *(const int2*)(cur + w * PITCH + tx2);
            acc[0][0] = __dp4a(a.x, b.x, acc[0][0]);
            acc[0][1] = __dp4a(a.x, b.y, acc[0][1]);
            acc[1][0] = __dp4a(a.y, b.x, acc[1][0]);
            acc[1][1] = __dp4a(a.y, b.y, acc[1][1]);
            acc[2][0] = __dp4a(a.z, b.x, acc[2][0]);
            acc[2][1] = __dp4a(a.z, b.y, acc[2][1]);
            acc[3][0] = __dp4a(a.w, b.x, acc[3][0]);
            acc[3][1] = __dp4a(a.w, b.y, acc[3][1]);
        }

        float2 cb = *(const float2*)(g_cbn4 + nt * BN + tx2);

#pragma unroll
        for (int i = 0; i < TM; i++) {
            float s0 = fmaf(m2r[i], (float)acc[i][0], cb.x);
            float s1 = fmaf(m2r[i], (float)acc[i][1], cb.y);
            float tmin = fminf(s0, s1);
            unsigned r = __reduce_min_sync(0xffffffffu, __float_as_uint(tmin));
            float wmin = __uint_as_float(r);
            rowmin[i] = fminf(rowmin[i], wmin);
            const float thr = rowmin[i] + MARGIN;
            if (wmin <= thr) {                    // warp-uniform guard
                const long grow = row0 + ty4 + i;
                if (s0 <= thr) {
                    int code = nt * BN + tx2;
                    atomicOr(&g_mask[grow * MW + (code >> 5)], 1u << (code & 31));
                }
                if (s1 <= thr) {
                    int code = nt * BN + tx2 + 1;
                    atomicOr(&g_mask[grow * MW + (code >> 5)], 1u << (code & 31));
                }
            }
        }
        __syncthreads();
    }
}

// ============================================================
// Kernel 3 (phase 2): exact rescoring from the bitmask (reference
// fp32 rounding chain: sequential fmaf k ascending;
// d = fl(fl(xn+cn) - fl(2m))), lowest-index tie-break.
// One warp per row; lane l owns mask words l and 32+l.
// total==1 -> that candidate IS the argmin (superset guarantee).
// ============================================================
__device__ __forceinline__ float exact_dist(const float* __restrict__ xr,
                                            const float* __restrict__ er,
                                            float xn, float cn) {
    float m = 0.f;
#pragma unroll 8
    for (int k = 0; k < K_DIM; k += 4) {
        float4 xv = *(const float4*)(xr + k);
        float4 ev = *(const float4*)(er + k);
        m = fmaf(xv.x, ev.x, m);
        m = fmaf(xv.y, ev.y, m);
        m = fmaf(xv.z, ev.z, m);
        m = fmaf(xv.w, ev.w, m);
    }
    return __fsub_rn(__fadd_rn(xn, cn), __fmul_rn(2.f, m));
}

__global__ void vq_phase2(const float* __restrict__ X,
                          const float* __restrict__ CB) {
    const int wid  = threadIdx.x >> 5;
    const int lane = threadIdx.x & 31;
    const long row = (long)blockIdx.x * 8 + wid;

    unsigned m0 = g_mask[row * MW + lane];
    unsigned m1 = g_mask[row * MW + 32 + lane];
    const int cnt = __popc(m0) + __popc(m1);
    const int total = __reduce_add_sync(0xffffffffu, cnt);

    if (total == 1) {
        if (cnt) {
            int code = m0 ? (lane * 32 + __ffs(m0) - 1)
                          : (1024 + lane * 32 + __ffs(m1) - 1);
            g_indices[row] = code;
        }
        return;
    }

    const float xn = g_xnorm[row];
    const float* xr = X + row * K_DIM;

    unsigned long long key = 0xFFFFFFFFFFFFFFFFULL;
    while (m0) {
        int b = __ffs(m0) - 1; m0 &= m0 - 1;
        int code = lane * 32 + b;
        float d = exact_dist(xr, CB + (long)code * K_DIM, xn, g_cbnorm[code]);
        unsigned long long k2 =
            ((unsigned long long)__float_as_uint(d) << 32) | (unsigned)code;
        if (k2 < key) key = k2;
    }
    while (m1) {
        int b = __ffs(m1) - 1; m1 &= m1 - 1;
        int code = 1024 + lane * 32 + b;
        float d = exact_dist(xr, CB + (long)code * K_DIM, xn, g_cbnorm[code]);
        unsigned long long k2 =
            ((unsigned long long)__float_as_uint(d) << 32) | (unsigned)code;
        if (k2 < key) key = k2;
    }
#pragma unroll
    for (int o = 16; o; o >>= 1) {
        unsigned long long other = __shfl_xor_sync(0xffffffffu, key, o);
        if (other < key) key = other;
    }
    if (lane == 0) g_indices[row] = (int)(key & 0xFFFFFFFFu);
}

// ============================================================
// Kernel 4: epilogue. One warp per row. quantized_st = fl(x + fl(q-x)),
// one-hot row in one pass, histogram, deterministic SSE partials.
// ============================================================
__global__ void vq_epilogue(const float* __restrict__ X,
                            const float* __restrict__ CB,
                            float* __restrict__ out) {
    __shared__ float warp_sse[8];
    const int wid  = threadIdx.x >> 5;
    const int lane = threadIdx.x & 31;
    const long row = (long)blockIdx.x * 8 + wid;
    const int idx = g_indices[row];

    const float4* xr = reinterpret_cast<const float4*>(X + row * K_DIM);
    const float4* cr = reinterpret_cast<const float4*>(CB + (long)idx * K_DIM);
    float* q = out + OFF_Q + row * K_DIM;

    float sse = 0.f;
#pragma unroll
    for (int t = 0; t < 2; t++) {
        int c4 = lane + 32 * t;
        float4 xv = xr[c4];
        float4 cv = cr[c4];
        float d0 = __fsub_rn(cv.x, xv.x);
        float d1 = __fsub_rn(cv.y, xv.y);
        float d2 = __fsub_rn(cv.z, xv.z);
        float d3 = __fsub_rn(cv.w, xv.w);
        q[c4 * 4 + 0] = __fadd_rn(xv.x, d0);
        q[c4 * 4 + 1] = __fadd_rn(xv.y, d1);
        q[c4 * 4 + 2] = __fadd_rn(xv.z, d2);
        q[c4 * 4 + 3] = __fadd_rn(xv.w, d3);
        sse += d0 * d0 + d1 * d1 + d2 * d2 + d3 * d3;
    }

    float2* enc = reinterpret_cast<float2*>(out + OFF_ENC + row * (long)N_CODES);
    const int hot_chunk = idx >> 1;
#pragma unroll
    for (int t = 0; t < 32; t++) {
        int c = lane + 32 * t;
        float2 v = make_float2(0.f, 0.f);
        if (c == hot_chunk) { if (idx & 1) v.y = 1.f; else v.x = 1.f; }
        enc[c] = v;
    }

#pragma unroll
    for (int o = 16; o; o >>= 1) sse += __shfl_xor_sync(0xffffffffu, sse, o);
    if (lane == 0) {
        atomicAdd(&g_hist[idx], 1);
        warp_sse[wid] = sse;
    }
    __syncthreads();
    if (threadIdx.x == 0) {
        double s = 0.0;
        for (int w = 0; w < 8; w++) s += (double)warp_sse[w];
        g_part[blockIdx.x] = s;
    }
}

// ============================================================
// Kernel 5: finalize loss + perplexity (1 block, deterministic)
// ============================================================
__global__ void vq_finalize(float* __restrict__ out) {
    __shared__ double sh[256];
    __shared__ double sh2[256];
    const int tid = threadIdx.x;

    double s = 0.0;
    for (int i = tid; i < EPI_BLOCKS; i += 256) s += g_part[i];
    sh[tid] = s;

    double ent = 0.0;
    for (int i = tid; i < N_CODES; i += 256) {
        double p = (double)g_hist[i] * (1.0 / (double)M_ROWS);
        ent -= p * log(p + 1e-10);
    }
    sh2[tid] = ent;
    __syncthreads();

    for (int st = 128; st; st >>= 1) {
        if (tid < st) { sh[tid] += sh[tid + st]; sh2[tid] += sh2[tid + st]; }
        __syncthreads();
    }
    if (tid == 0) {
        double mse = sh[0] / ((double)M_ROWS * (double)K_DIM);
        out[0]        = (float)(1.25 * mse);
        out[OFF_PERP] = (float)exp(sh2[0]);
    }
}

// ============================================================
extern "C" void kernel_launch(void* const* d_in, const int* in_sizes, int n_in,
                              void* d_out, int out_size) {
    const float* X  = (const float*)d_in[0];
    const float* CB = (const float*)d_in[1];
    float* out = (float*)d_out;

    cudaFuncSetAttribute(vq_phase1,
                         cudaFuncAttributeMaxDynamicSharedMemorySize, SM_TOTAL);

    vq_init<<<8, 256>>>(CB);
    vq_xnorm<<<M_ROWS / 256, 256>>>(X);
    vq_xpack<<<M_ROWS * KW / 256, 256>>>(X);
    vq_phase1<<<M_ROWS / BM, 512, SM_TOTAL>>>();
    vq_phase2<<<M_ROWS / 8, 256>>>(X, CB);
    vq_epilogue<<<EPI_BLOCKS, 256>>>(X, CB, out);
    vq_finalize<<<1, 256>>>(out);
}